// round 7
// baseline (speedup 1.0000x reference)
#include <cuda_runtime.h>
#include <cuda_bf16.h>
#include <math.h>

// ---------------------------------------------------------------------------
// Problem constants
// ---------------------------------------------------------------------------
#define TSEQ 16384          // L per mamba sequence (M*N)
#define NSEQ 4              // 2 batches x 2 directions
#define TTOK 65536          // NSEQ*TSEQ
#define TOK2 32768          // output tokens (B*M*N)
#define CCH  96
#define DI   192
#define DS   16
#define NXD  38             // dtr(6) + 2*ds(32)
#define DTR  6
#define NCH  128            // scan chunks per sequence
#define LCH  128            // chunk length
#define LOG2E 1.4426950408889634f

// ---------------------------------------------------------------------------
// Scratch (static device globals; no allocation allowed)
// ---------------------------------------------------------------------------
static __device__ __align__(256) float g_cbuf  [(size_t)TTOK*CCH];
static __device__ __align__(256) float g_tcat  [(size_t)TTOK*CCH];
static __device__ __align__(256) float g_xz    [(size_t)TTOK*384];
static __device__ __align__(256) float g_xc    [(size_t)TTOK*DI];
static __device__ __align__(256) float g_xdbl  [(size_t)TTOK*NXD];
static __device__ __align__(256) float g_dt    [(size_t)TTOK*DI];
static __device__ __align__(256) float g_y     [(size_t)TTOK*DI];
static __device__ __align__(256) float g_mo    [(size_t)TTOK*CCH];
static __device__ __align__(256) float g_outssm[(size_t)TOK2*CCH];
static __device__ __align__(256) float g_lnbuf [(size_t)TOK2*CCH];
static __device__ __align__(256) float g_mid   [(size_t)TOK2*CCH];
static __device__ __align__(256) float g_hend  [NSEQ*NCH*DI*DS];
static __device__ __align__(256) float g_P     [NSEQ*NCH*DI*DS];
static __device__ __align__(256) float g_h0    [NSEQ*NCH*DI*DS];

// ---------------------------------------------------------------------------
// helpers
// ---------------------------------------------------------------------------
__device__ __forceinline__ float ex2f(float x) {
    float y;
    asm("ex2.approx.f32 %0, %1;" : "=f"(y) : "f"(x));
    return y;
}
__device__ __forceinline__ float siluf(float x) {
    return x / (1.0f + expf(-x));
}
__device__ __forceinline__ float softplusf(float x) {
    return (x > 20.0f) ? x : log1pf(expf(x));
}
__device__ __forceinline__ float geluf(float x) {
    return 0.5f * x * (1.0f + erff(x * 0.7071067811865476f));
}
__device__ __forceinline__ unsigned f2tf(float x) {
    unsigned r;
    asm("cvt.rna.tf32.f32 %0, %1;" : "=r"(r) : "f"(x));
    return r;
}
// D += A(16x8,row) * B(8x8,col) tf32
__device__ __forceinline__ void mma8(float* c, const unsigned* a,
                                     unsigned b0, unsigned b1) {
    asm volatile(
        "mma.sync.aligned.m16n8k8.row.col.f32.tf32.tf32.f32 "
        "{%0,%1,%2,%3}, {%4,%5,%6,%7}, {%8,%9}, {%0,%1,%2,%3};"
        : "+f"(c[0]), "+f"(c[1]), "+f"(c[2]), "+f"(c[3])
        : "r"(a[0]), "r"(a[1]), "r"(a[2]), "r"(a[3]), "r"(b0), "r"(b1));
}

// ---------------------------------------------------------------------------
// TF32 GEMM: out[M,N] = act(A[M,K] @ W[N,K]^T + bias) + res
// BM=128, BN in {96,48}. 8 warps; warp tile 32 x (BN/2).
// M%128==0, K%16==0. ACT: 0=none, 1=gelu.
// ---------------------------------------------------------------------------
template <int BN, int ACT, bool HASB, bool HASR>
__global__ __launch_bounds__(256) void gemm_tf32_kernel(
    const float* __restrict__ A, const float* __restrict__ W,
    const float* __restrict__ bias, const float* __restrict__ res,
    float* __restrict__ out, int M, int N, int K)
{
    constexpr int NF = BN / 16;         // n-frags per warp (96->6, 48->3)
    constexpr int SW = BN + 8;
    __shared__ unsigned As[2][16][136];
    __shared__ unsigned Ws[2][16][SW];

    int tid = threadIdx.x, lane = tid & 31, warp = tid >> 5;
    int wm = warp >> 1, wn = warp & 1;
    int qr = lane >> 2, qc = lane & 3;
    int m0 = blockIdx.x * 128, n0 = blockIdx.y * BN;

    float acc[2][NF][4];
#pragma unroll
    for (int i = 0; i < 2; i++)
#pragma unroll
        for (int j = 0; j < NF; j++)
#pragma unroll
            for (int q = 0; q < 4; q++) acc[i][j][q] = 0.f;

    float4 pa[2], pw[2];
    const int fA0 = tid, fA1 = tid + 256;
    const int mA0 = fA0 & 127, qA0 = fA0 >> 7;
    const int mA1 = fA1 & 127, qA1 = fA1 >> 7;
    const int fW1 = tid + 256;
    const int nW0 = tid % BN, qW0 = tid / BN;
    const int nW1 = fW1 % BN, qW1 = fW1 / BN;
    const bool hasW0 = (tid < BN * 4);
    const bool hasW1 = (fW1 < BN * 4);

    const int nk = K / 16;

    // ---- prologue: load + store tile 0 ----
    {
        pa[0] = *(const float4*)&A[(size_t)(m0 + mA0) * K + qA0 * 4];
        pa[1] = *(const float4*)&A[(size_t)(m0 + mA1) * K + qA1 * 4];
        if (hasW0) {
            float4 v = make_float4(0.f,0.f,0.f,0.f);
            if (n0 + nW0 < N) v = *(const float4*)&W[(size_t)(n0 + nW0) * K + qW0 * 4];
            pw[0] = v;
        }
        if (hasW1) {
            float4 v = make_float4(0.f,0.f,0.f,0.f);
            if (n0 + nW1 < N) v = *(const float4*)&W[(size_t)(n0 + nW1) * K + qW1 * 4];
            pw[1] = v;
        }
        As[0][qA0*4+0][mA0] = f2tf(pa[0].x); As[0][qA0*4+1][mA0] = f2tf(pa[0].y);
        As[0][qA0*4+2][mA0] = f2tf(pa[0].z); As[0][qA0*4+3][mA0] = f2tf(pa[0].w);
        As[0][qA1*4+0][mA1] = f2tf(pa[1].x); As[0][qA1*4+1][mA1] = f2tf(pa[1].y);
        As[0][qA1*4+2][mA1] = f2tf(pa[1].z); As[0][qA1*4+3][mA1] = f2tf(pa[1].w);
        if (hasW0) {
            Ws[0][qW0*4+0][nW0] = f2tf(pw[0].x); Ws[0][qW0*4+1][nW0] = f2tf(pw[0].y);
            Ws[0][qW0*4+2][nW0] = f2tf(pw[0].z); Ws[0][qW0*4+3][nW0] = f2tf(pw[0].w);
        }
        if (hasW1) {
            Ws[0][qW1*4+0][nW1] = f2tf(pw[1].x); Ws[0][qW1*4+1][nW1] = f2tf(pw[1].y);
            Ws[0][qW1*4+2][nW1] = f2tf(pw[1].z); Ws[0][qW1*4+3][nW1] = f2tf(pw[1].w);
        }
    }
    __syncthreads();

    for (int kt = 0; kt < nk; kt++) {
        int buf = kt & 1;
        bool more = (kt + 1 < nk);
        if (more) {
            int k0 = (kt + 1) * 16;
            pa[0] = *(const float4*)&A[(size_t)(m0 + mA0) * K + k0 + qA0 * 4];
            pa[1] = *(const float4*)&A[(size_t)(m0 + mA1) * K + k0 + qA1 * 4];
            if (hasW0) {
                float4 v = make_float4(0.f,0.f,0.f,0.f);
                if (n0 + nW0 < N) v = *(const float4*)&W[(size_t)(n0 + nW0) * K + k0 + qW0 * 4];
                pw[0] = v;
            }
            if (hasW1) {
                float4 v = make_float4(0.f,0.f,0.f,0.f);
                if (n0 + nW1 < N) v = *(const float4*)&W[(size_t)(n0 + nW1) * K + k0 + qW1 * 4];
                pw[1] = v;
            }
        }

        // compute on buf
#pragma unroll
        for (int ks = 0; ks < 2; ks++) {
            int kb = ks * 8;
            unsigned a[2][4];
#pragma unroll
            for (int mt = 0; mt < 2; mt++) {
                int r = wm * 32 + mt * 16 + qr;
                a[mt][0] = As[buf][kb + qc][r];
                a[mt][1] = As[buf][kb + qc][r + 8];
                a[mt][2] = As[buf][kb + qc + 4][r];
                a[mt][3] = As[buf][kb + qc + 4][r + 8];
            }
#pragma unroll
            for (int nt = 0; nt < NF; nt++) {
                int cn = wn * (NF * 8) + nt * 8 + qr;
                unsigned b0 = Ws[buf][kb + qc][cn];
                unsigned b1 = Ws[buf][kb + qc + 4][cn];
                mma8(acc[0][nt], a[0], b0, b1);
                mma8(acc[1][nt], a[1], b0, b1);
            }
        }

        if (more) {
            int nb = buf ^ 1;
            As[nb][qA0*4+0][mA0] = f2tf(pa[0].x); As[nb][qA0*4+1][mA0] = f2tf(pa[0].y);
            As[nb][qA0*4+2][mA0] = f2tf(pa[0].z); As[nb][qA0*4+3][mA0] = f2tf(pa[0].w);
            As[nb][qA1*4+0][mA1] = f2tf(pa[1].x); As[nb][qA1*4+1][mA1] = f2tf(pa[1].y);
            As[nb][qA1*4+2][mA1] = f2tf(pa[1].z); As[nb][qA1*4+3][mA1] = f2tf(pa[1].w);
            if (hasW0) {
                Ws[nb][qW0*4+0][nW0] = f2tf(pw[0].x); Ws[nb][qW0*4+1][nW0] = f2tf(pw[0].y);
                Ws[nb][qW0*4+2][nW0] = f2tf(pw[0].z); Ws[nb][qW0*4+3][nW0] = f2tf(pw[0].w);
            }
            if (hasW1) {
                Ws[nb][qW1*4+0][nW1] = f2tf(pw[1].x); Ws[nb][qW1*4+1][nW1] = f2tf(pw[1].y);
                Ws[nb][qW1*4+2][nW1] = f2tf(pw[1].z); Ws[nb][qW1*4+3][nW1] = f2tf(pw[1].w);
            }
            __syncthreads();
        }
    }

    // epilogue
#pragma unroll
    for (int mt = 0; mt < 2; mt++) {
        int r = m0 + wm * 32 + mt * 16 + qr;
#pragma unroll
        for (int nt = 0; nt < NF; nt++) {
            int c = n0 + wn * (NF * 8) + nt * 8 + 2 * qc;
            if (c >= N) continue;
            bool two = (c + 1 < N);
            float b0v = HASB ? bias[c] : 0.f;
            float b1v = (HASB && two) ? bias[c + 1] : 0.f;
            size_t ro0 = (size_t)r * N, ro1 = (size_t)(r + 8) * N;
            float v00 = acc[mt][nt][0] + b0v;
            float v01 = acc[mt][nt][1] + b1v;
            float v10 = acc[mt][nt][2] + b0v;
            float v11 = acc[mt][nt][3] + b1v;
            if (ACT == 1) { v00 = geluf(v00); v01 = geluf(v01);
                            v10 = geluf(v10); v11 = geluf(v11); }
            if (HASR) {
                v00 += res[ro0 + c]; v10 += res[ro1 + c];
                if (two) { v01 += res[ro0 + c + 1]; v11 += res[ro1 + c + 1]; }
            }
            out[ro0 + c] = v00;
            out[ro1 + c] = v10;
            if (two) { out[ro0 + c + 1] = v01; out[ro1 + c + 1] = v11; }
        }
    }
}

// ---------------------------------------------------------------------------
// Conv 1x3 over the N dim via tf32 MMA (3 shifted-A matmuls). Both directions
// in one launch: dir = blockIdx.x >> 8.
// ---------------------------------------------------------------------------
__global__ __launch_bounds__(256) void conv13_mma_kernel(
    const float* __restrict__ x,
    const float* __restrict__ w0, const float* __restrict__ b0,
    const float* __restrict__ w1, const float* __restrict__ b1)
{
    int dir = blockIdx.x >> 8;
    int bi  = blockIdx.x & 255;
    const float* w    = dir ? w1 : w0;
    const float* bias = dir ? b1 : b0;

    int bm = bi >> 3;                  // b*16 + m  (0..31)
    int n0 = (bi & 7) << 7;            // n tile start (0..896)
    int b  = bm >> 4, m_img = bm & 15;

    __shared__ unsigned As[16][136];       // As[cin][p], p = n-n0+1 (130 used)
    __shared__ unsigned Ws3[3][16][104];   // Ws3[tap][cin][cout]

    int tid = threadIdx.x, lane = tid & 31, warp = tid >> 5;
    int wm = warp >> 1, wn = warp & 1;
    int qr = lane >> 2, qc = lane & 3;

    float acc[2][6][4];
#pragma unroll
    for (int i = 0; i < 2; i++)
#pragma unroll
        for (int j = 0; j < 6; j++)
#pragma unroll
            for (int q = 0; q < 4; q++) acc[i][j][q] = 0.f;

    const float* xrow = x + (size_t)bm * 1024 * CCH;

    for (int c0 = 0; c0 < CCH; c0 += 16) {
        for (int f = tid; f < 520; f += 256) {
            int q = f / 130, p = f - q * 130;
            int n = n0 - 1 + p;
            float4 v = make_float4(0.f, 0.f, 0.f, 0.f);
            if (n >= 0 && n < 1024)
                v = *(const float4*)&xrow[(size_t)n * CCH + c0 + q * 4];
            As[q*4+0][p] = f2tf(v.x); As[q*4+1][p] = f2tf(v.y);
            As[q*4+2][p] = f2tf(v.z); As[q*4+3][p] = f2tf(v.w);
        }
        for (int f = tid; f < 4608; f += 256) {
            int tap = f / 1536, r = f - tap * 1536;
            int k = r / 96, cout = r - k * 96;
            Ws3[tap][k][cout] =
                f2tf(w[((size_t)cout * CCH + (c0 + k)) * 3 + tap]);
        }
        __syncthreads();

#pragma unroll
        for (int ks = 0; ks < 2; ks++) {
            int kb = ks * 8;
#pragma unroll
            for (int tap = 0; tap < 3; tap++) {
                int off = dir ? (1 - tap) : (tap - 1);
                unsigned a[2][4];
#pragma unroll
                for (int mt = 0; mt < 2; mt++) {
                    int r = wm * 32 + mt * 16 + qr + 1 + off;
                    a[mt][0] = As[kb + qc][r];
                    a[mt][1] = As[kb + qc][r + 8];
                    a[mt][2] = As[kb + qc + 4][r];
                    a[mt][3] = As[kb + qc + 4][r + 8];
                }
#pragma unroll
                for (int nt = 0; nt < 6; nt++) {
                    int cn = wn * 48 + nt * 8 + qr;
                    unsigned bb0 = Ws3[tap][kb + qc][cn];
                    unsigned bb1 = Ws3[tap][kb + qc + 4][cn];
                    mma8(acc[0][nt], a[0], bb0, bb1);
                    mma8(acc[1][nt], a[1], bb0, bb1);
                }
            }
        }
        __syncthreads();
    }

    int seq = dir * 2 + b;
    size_t lbase = (size_t)seq * TSEQ + (size_t)m_img * 1024 + n0;
#pragma unroll
    for (int mt = 0; mt < 2; mt++) {
        int tr = wm * 32 + mt * 16 + qr;
        size_t ro0 = (lbase + tr) * CCH;
        size_t ro1 = (lbase + tr + 8) * CCH;
#pragma unroll
        for (int nt = 0; nt < 6; nt++) {
            int c = wn * 48 + nt * 8 + 2 * qc;
            float bc0 = bias[c], bc1 = bias[c + 1];
            float2 s0 = make_float2(acc[mt][nt][0] + bc0, acc[mt][nt][1] + bc1);
            float2 s1 = make_float2(acc[mt][nt][2] + bc0, acc[mt][nt][3] + bc1);
            *(float2*)&g_cbuf[ro0 + c] = s0;
            *(float2*)&g_cbuf[ro1 + c] = s1;
        }
    }
}

// ---------------------------------------------------------------------------
// LayerNorm over 96 channels, warp per row. 256 thr = 8 rows/block.
// ---------------------------------------------------------------------------
__global__ __launch_bounds__(256) void ln_kernel(
    const float* __restrict__ in, float* __restrict__ out,
    const float* __restrict__ g, const float* __restrict__ bta, int rows)
{
    int row = blockIdx.x * 8 + (threadIdx.x >> 5);
    if (row >= rows) return;
    int lane = threadIdx.x & 31;
    const float* r = in + (size_t)row * CCH;
    float v0 = r[lane], v1 = r[lane+32], v2 = r[lane+64];
    float s = v0 + v1 + v2;
#pragma unroll
    for (int off = 16; off; off >>= 1) s += __shfl_xor_sync(0xffffffffu, s, off);
    float mu = s * (1.f/96.f);
    float d0 = v0-mu, d1 = v1-mu, d2 = v2-mu;
    float q = d0*d0 + d1*d1 + d2*d2;
#pragma unroll
    for (int off = 16; off; off >>= 1) q += __shfl_xor_sync(0xffffffffu, q, off);
    float rs = rsqrtf(q * (1.f/96.f) + 1e-5f);
    float* o = out + (size_t)row * CCH;
    o[lane]    = d0 * rs * g[lane]    + bta[lane];
    o[lane+32] = d1 * rs * g[lane+32] + bta[lane+32];
    o[lane+64] = d2 * rs * g[lane+64] + bta[lane+64];
}

// ---------------------------------------------------------------------------
// Fused combine + LayerNorm:
// ssm = mo[t] + mo[t+32768] + tcat[t] + tcat[t+32768]  -> g_outssm
// lnbuf = LN(ssm)                                       -> g_lnbuf
// warp per row.
// ---------------------------------------------------------------------------
__global__ __launch_bounds__(256) void combine_ln_kernel(
    const float* __restrict__ g, const float* __restrict__ bta)
{
    int row = blockIdx.x * 8 + (threadIdx.x >> 5);
    int lane = threadIdx.x & 31;
    size_t lo = (size_t)row * CCH;
    size_t hi = lo + (size_t)TOK2 * CCH;
    float v0 = g_mo[lo+lane]    + g_mo[hi+lane]    + g_tcat[lo+lane]    + g_tcat[hi+lane];
    float v1 = g_mo[lo+lane+32] + g_mo[hi+lane+32] + g_tcat[lo+lane+32] + g_tcat[hi+lane+32];
    float v2 = g_mo[lo+lane+64] + g_mo[hi+lane+64] + g_tcat[lo+lane+64] + g_tcat[hi+lane+64];
    g_outssm[lo+lane]    = v0;
    g_outssm[lo+lane+32] = v1;
    g_outssm[lo+lane+64] = v2;
    float s = v0 + v1 + v2;
#pragma unroll
    for (int off = 16; off; off >>= 1) s += __shfl_xor_sync(0xffffffffu, s, off);
    float mu = s * (1.f/96.f);
    float d0 = v0-mu, d1 = v1-mu, d2 = v2-mu;
    float q = d0*d0 + d1*d1 + d2*d2;
#pragma unroll
    for (int off = 16; off; off >>= 1) q += __shfl_xor_sync(0xffffffffu, q, off);
    float rs = rsqrtf(q * (1.f/96.f) + 1e-5f);
    g_lnbuf[lo+lane]    = d0 * rs * g[lane]    + bta[lane];
    g_lnbuf[lo+lane+32] = d1 * rs * g[lane+32] + bta[lane+32];
    g_lnbuf[lo+lane+64] = d2 * rs * g[lane+64] + bta[lane+64];
}

// ---------------------------------------------------------------------------
// Depthwise causal conv1d (k=4) + bias + silu, vectorized float4 over d.
// One thread = 1 token x 4 channels. grid*block = TTOK*48.
// ---------------------------------------------------------------------------
__global__ __launch_bounds__(256) void conv1d_kernel(
    const float* __restrict__ xz, const float* __restrict__ w,
    const float* __restrict__ b)
{
    int idx = blockIdx.x * 256 + threadIdx.x;     // tok*48 + d4
    int tok = idx / 48, d4 = idx - tok * 48;
    int d = d4 * 4;
    int pos = tok & (TSEQ - 1);

    float4 wv[4];
#pragma unroll
    for (int j = 0; j < 4; j++)
        wv[j] = *(const float4*)&w[(d + j) * 4];   // 4 taps of channel d+j

    float4 acc = *(const float4*)&b[d];
#pragma unroll
    for (int t = 0; t < 4; t++) {
        int p = pos - 3 + t;
        if (p >= 0) {
            float4 xv = *(const float4*)&xz[(size_t)(tok - 3 + t) * 384 + d];
            acc.x = fmaf(((const float*)&wv[0])[t], xv.x, acc.x);
            acc.y = fmaf(((const float*)&wv[1])[t], xv.y, acc.y);
            acc.z = fmaf(((const float*)&wv[2])[t], xv.z, acc.z);
            acc.w = fmaf(((const float*)&wv[3])[t], xv.w, acc.w);
        }
    }
    float4 o;
    o.x = siluf(acc.x); o.y = siluf(acc.y);
    o.z = siluf(acc.z); o.w = siluf(acc.w);
    *(float4*)&g_xc[(size_t)tok * DI + d] = o;
}

// ---------------------------------------------------------------------------
// dt = softplus(x_dbl[:, :6] @ dt_proj_w^T + dt_proj_b), vectorized:
// one thread = 1 token x 4 d's.
// ---------------------------------------------------------------------------
__global__ __launch_bounds__(256) void dt_kernel(
    const float* __restrict__ dtw, const float* __restrict__ dtb)
{
    int idx = blockIdx.x * 256 + threadIdx.x;     // tok*48 + d4
    int tok = idx / 48, d4 = idx - tok * 48;
    int d = d4 * 4;

    const float* xr = &g_xdbl[(size_t)tok * NXD];
    float x0 = xr[0], x1 = xr[1], x2 = xr[2];
    float x3 = xr[3], x4 = xr[4], x5 = xr[5];

    float4 o;
#pragma unroll
    for (int j = 0; j < 4; j++) {
        const float* wr = &dtw[(d + j) * DTR];
        float acc = dtb[d + j];
        acc = fmaf(wr[0], x0, acc); acc = fmaf(wr[1], x1, acc);
        acc = fmaf(wr[2], x2, acc); acc = fmaf(wr[3], x3, acc);
        acc = fmaf(wr[4], x4, acc); acc = fmaf(wr[5], x5, acc);
        ((float*)&o)[j] = softplusf(acc);
    }
    *(float4*)&g_dt[(size_t)tok * DI + d] = o;
}

// ---------------------------------------------------------------------------
// Scan S1: per (seq,chunk) block of 192 threads (one per d).
// ---------------------------------------------------------------------------
__global__ __launch_bounds__(192) void scan1_kernel(const float* __restrict__ A_log)
{
    int seq = blockIdx.x >> 7, ch = blockIdx.x & 127;
    int d = threadIdx.x;
    int tok0 = seq * TSEQ + ch * LCH;

    __shared__ __align__(16) float Bs[LCH][DS];
    for (int f = d; f < LCH*DS; f += 192) {
        int l = f >> 4, s = f & 15;
        Bs[l][s] = g_xdbl[(size_t)(tok0 + l) * NXD + DTR + s];
    }
    __syncthreads();

    float aa[DS], h[DS];
#pragma unroll
    for (int s = 0; s < DS; s++) {
        aa[s] = -expf(A_log[d*DS + s]) * LOG2E;
        h[s] = 0.f;
    }
    float dtsum = 0.f;

    for (int l = 0; l < LCH; l++) {
        int tok = tok0 + l;
        float dt = g_dt[(size_t)tok * DI + d];
        float u  = g_xc[(size_t)tok * DI + d];
        float du = dt * u;
        dtsum += dt;
        float bl[DS];
#pragma unroll
        for (int q = 0; q < 4; q++) {
            float4 v = *(const float4*)&Bs[l][q*4];
            bl[q*4]=v.x; bl[q*4+1]=v.y; bl[q*4+2]=v.z; bl[q*4+3]=v.w;
        }
#pragma unroll
        for (int s = 0; s < DS; s++) {
            float e = ex2f(aa[s] * dt);
            h[s] = fmaf(e, h[s], du * bl[s]);
        }
    }
    size_t base = ((size_t)(seq*NCH + ch) * DI + d) * DS;
#pragma unroll
    for (int s = 0; s < DS; s++) {
        g_hend[base + s] = h[s];
        g_P[base + s]    = ex2f(aa[s] * dtsum);
    }
}

// ---------------------------------------------------------------------------
// Scan S2: sequential cross-chunk combine; thread per (seq,d,s).
// ---------------------------------------------------------------------------
__global__ __launch_bounds__(256) void scan2_kernel()
{
    int idx = blockIdx.x * 256 + threadIdx.x;     // seq*3072 + d*16 + s
    int seq = idx / (DI*DS), ds_ = idx - seq * (DI*DS);
    float H = 0.f;
#pragma unroll 4
    for (int c = 0; c < NCH; c++) {
        size_t base = (size_t)(seq*NCH + c) * (DI*DS) + ds_;
        g_h0[base] = H;
        H = fmaf(g_P[base], H, g_hend[base]);
    }
}

// ---------------------------------------------------------------------------
// Scan S3: recompute local scan with initial state h0, emit
// yg = (y + u*Dp) * silu(z)  into g_y.
// ---------------------------------------------------------------------------
__global__ __launch_bounds__(192) void scan3_kernel(
    const float* __restrict__ A_log, const float* __restrict__ Dp)
{
    int seq = blockIdx.x >> 7, ch = blockIdx.x & 127;
    int d = threadIdx.x;
    int tok0 = seq * TSEQ + ch * LCH;

    __shared__ __align__(16) float Bs[LCH][DS];
    __shared__ __align__(16) float Cs[LCH][DS];
    for (int f = d; f < LCH*DS; f += 192) {
        int l = f >> 4, s = f & 15;
        size_t r = (size_t)(tok0 + l) * NXD + DTR;
        Bs[l][s] = g_xdbl[r + s];
        Cs[l][s] = g_xdbl[r + DS + s];
    }
    __syncthreads();

    float aa[DS], h[DS];
    size_t base = ((size_t)(seq*NCH + ch) * DI + d) * DS;
#pragma unroll
    for (int s = 0; s < DS; s++) {
        aa[s] = -expf(A_log[d*DS + s]) * LOG2E;
        h[s] = g_h0[base + s];
    }
    float dval = Dp[d];

    for (int l = 0; l < LCH; l++) {
        int tok = tok0 + l;
        float dt = g_dt[(size_t)tok * DI + d];
        float u  = g_xc[(size_t)tok * DI + d];
        float du = dt * u;
        float bl[DS], cl[DS];
#pragma unroll
        for (int q = 0; q < 4; q++) {
            float4 v = *(const float4*)&Bs[l][q*4];
            bl[q*4]=v.x; bl[q*4+1]=v.y; bl[q*4+2]=v.z; bl[q*4+3]=v.w;
            float4 c = *(const float4*)&Cs[l][q*4];
            cl[q*4]=c.x; cl[q*4+1]=c.y; cl[q*4+2]=c.z; cl[q*4+3]=c.w;
        }
        float y = 0.f;
#pragma unroll
        for (int s = 0; s < DS; s++) {
            float e = ex2f(aa[s] * dt);
            h[s] = fmaf(e, h[s], du * bl[s]);
            y = fmaf(h[s], cl[s], y);
        }
        y = fmaf(u, dval, y);
        float z = g_xz[(size_t)tok * 384 + DI + d];
        g_y[(size_t)tok * DI + d] = y * siluf(z);
    }
}

// ---------------------------------------------------------------------------
extern "C" void kernel_launch(void* const* d_in, const int* in_sizes, int n_in,
                              void* d_out, int out_size) {
    const float* x          = (const float*)d_in[0];
    const float* conv1234_w = (const float*)d_in[1];
    const float* conv1234_b = (const float*)d_in[2];
    const float* conv4321_w = (const float*)d_in[3];
    const float* conv4321_b = (const float*)d_in[4];
    const float* ln_g       = (const float*)d_in[5];
    const float* ln_b       = (const float*)d_in[6];
    const float* in_proj_w  = (const float*)d_in[7];
    const float* conv1d_w   = (const float*)d_in[8];
    const float* conv1d_b   = (const float*)d_in[9];
    const float* x_proj_w   = (const float*)d_in[10];
    const float* dt_proj_w  = (const float*)d_in[11];
    const float* dt_proj_b  = (const float*)d_in[12];
    const float* A_log      = (const float*)d_in[13];
    const float* Dp         = (const float*)d_in[14];
    const float* out_proj_w = (const float*)d_in[15];
    const float* fc1_w      = (const float*)d_in[16];
    const float* fc1_b      = (const float*)d_in[17];
    const float* fc2_w      = (const float*)d_in[18];
    const float* fc2_b      = (const float*)d_in[19];
    float* out = (float*)d_out;

    float *cbuf, *tcat, *xz, *xc, *y, *mo, *outssm, *lnbuf, *mid;
    cudaGetSymbolAddress((void**)&cbuf,   g_cbuf);
    cudaGetSymbolAddress((void**)&tcat,   g_tcat);
    cudaGetSymbolAddress((void**)&xz,     g_xz);
    cudaGetSymbolAddress((void**)&xc,     g_xc);
    float *xdbl; cudaGetSymbolAddress((void**)&xdbl, g_xdbl);
    cudaGetSymbolAddress((void**)&y,      g_y);
    cudaGetSymbolAddress((void**)&mo,     g_mo);
    cudaGetSymbolAddress((void**)&outssm, g_outssm);
    cudaGetSymbolAddress((void**)&lnbuf,  g_lnbuf);
    cudaGetSymbolAddress((void**)&mid,    g_mid);

    // 1) conv 1x3 both directions (one launch) -> g_cbuf [4 seqs][16384][96]
    conv13_mma_kernel<<<512, 256>>>(x, conv1234_w, conv1234_b,
                                    conv4321_w, conv4321_b);

    // 2) LN -> g_tcat (t1 stacked with t2, 65536 rows)
    ln_kernel<<<TTOK/8, 256>>>(cbuf, tcat, ln_g, ln_b, TTOK);

    // 3) in_proj: [65536,96] @ [384,96]^T -> g_xz
    {
        dim3 grid(TTOK/128, 4);
        gemm_tf32_kernel<96,0,false,false><<<grid, 256>>>(tcat, in_proj_w, nullptr, nullptr, xz, TTOK, 384, CCH);
    }

    // 4) depthwise conv1d + silu -> g_xc (vectorized)
    conv1d_kernel<<<(TTOK*48)/256, 256>>>(xz, conv1d_w, conv1d_b);

    // 5) x_proj: [65536,192] @ [38,192]^T -> g_xdbl  (BN=48 tile)
    {
        dim3 grid(TTOK/128, 1);
        gemm_tf32_kernel<48,0,false,false><<<grid, 256>>>(xc, x_proj_w, nullptr, nullptr, xdbl, TTOK, NXD, DI);
    }

    // 6) dt projection + softplus -> g_dt (vectorized)
    dt_kernel<<<(TTOK*48)/256, 256>>>(dt_proj_w, dt_proj_b);

    // 7-9) chunked selective scan
    scan1_kernel<<<NSEQ*NCH, 192>>>(A_log);
    scan2_kernel<<<(NSEQ*DI*DS)/256, 256>>>();
    scan3_kernel<<<NSEQ*NCH, 192>>>(A_log, Dp);

    // 10) out_proj: [65536,192] @ [96,192]^T -> g_mo
    {
        dim3 grid(TTOK/128, 1);
        gemm_tf32_kernel<96,0,false,false><<<grid, 256>>>(y, out_proj_w, nullptr, nullptr, mo, TTOK, CCH, DI);
    }

    // 11+12) fused combine + LN -> g_outssm, g_lnbuf
    combine_ln_kernel<<<TOK2/8, 256>>>(ln_g, ln_b);

    // 13) fc1 + gelu -> g_mid
    {
        dim3 grid(TOK2/128, 1);
        gemm_tf32_kernel<96,1,true,false><<<grid, 256>>>(lnbuf, fc1_w, fc1_b, nullptr, mid, TOK2, CCH, CCH);
    }

    // 14) fc2 + bias + residual(out_ssm) -> d_out
    {
        dim3 grid(TOK2/128, 1);
        gemm_tf32_kernel<96,0,true,true><<<grid, 256>>>(mid, fc2_w, fc2_b, outssm, out, TOK2, CCH, CCH);
    }
}

// round 8
// speedup vs baseline: 1.1147x; 1.1147x over previous
#include <cuda_runtime.h>
#include <cuda_bf16.h>
#include <math.h>

// ---------------------------------------------------------------------------
// Problem constants
// ---------------------------------------------------------------------------
#define TSEQ 16384          // L per mamba sequence (M*N)
#define NSEQ 4              // 2 batches x 2 directions
#define TTOK 65536          // NSEQ*TSEQ
#define TOK2 32768          // output tokens (B*M*N)
#define CCH  96
#define DI   192
#define DS   16
#define NXD  38             // dtr(6) + 2*ds(32)
#define DTR  6
#define NCH  128            // scan chunks per sequence
#define LCH  128            // chunk length
#define LOG2E 1.4426950408889634f

// ---------------------------------------------------------------------------
// Scratch (static device globals; no allocation allowed)
// ---------------------------------------------------------------------------
static __device__ __align__(256) float g_cbuf  [(size_t)TTOK*CCH];
static __device__ __align__(256) float g_tcat  [(size_t)TTOK*CCH];
static __device__ __align__(256) float g_xz    [(size_t)TTOK*384];
static __device__ __align__(256) float g_xc    [(size_t)TTOK*DI];
static __device__ __align__(256) float g_xdbl  [(size_t)TTOK*NXD];
static __device__ __align__(256) float g_dt    [(size_t)TTOK*DI];
static __device__ __align__(256) float g_y     [(size_t)TTOK*DI];
static __device__ __align__(256) float g_mo    [(size_t)TTOK*CCH];
static __device__ __align__(256) float g_outssm[(size_t)TOK2*CCH];
static __device__ __align__(256) float g_lnbuf [(size_t)TOK2*CCH];
static __device__ __align__(256) float g_mid   [(size_t)TOK2*CCH];
static __device__ __align__(256) float g_hend  [NSEQ*NCH*DI*DS];
static __device__ __align__(256) float g_P     [NSEQ*NCH*DI*DS];
static __device__ __align__(256) float g_h0    [NSEQ*NCH*DI*DS];

// ---------------------------------------------------------------------------
// helpers
// ---------------------------------------------------------------------------
__device__ __forceinline__ float ex2f(float x) {
    float y;
    asm("ex2.approx.f32 %0, %1;" : "=f"(y) : "f"(x));
    return y;
}
__device__ __forceinline__ float siluf(float x) {
    return x / (1.0f + expf(-x));
}
__device__ __forceinline__ float softplusf(float x) {
    return (x > 20.0f) ? x : log1pf(expf(x));
}
__device__ __forceinline__ float geluf(float x) {
    return 0.5f * x * (1.0f + erff(x * 0.7071067811865476f));
}
__device__ __forceinline__ unsigned f2tf(float x) {
    unsigned r;
    asm("cvt.rna.tf32.f32 %0, %1;" : "=r"(r) : "f"(x));
    return r;
}
// D += A(16x8,row) * B(8x8,col) tf32
__device__ __forceinline__ void mma8(float* c, const unsigned* a,
                                     unsigned b0, unsigned b1) {
    asm volatile(
        "mma.sync.aligned.m16n8k8.row.col.f32.tf32.tf32.f32 "
        "{%0,%1,%2,%3}, {%4,%5,%6,%7}, {%8,%9}, {%0,%1,%2,%3};"
        : "+f"(c[0]), "+f"(c[1]), "+f"(c[2]), "+f"(c[3])
        : "r"(a[0]), "r"(a[1]), "r"(a[2]), "r"(a[3]), "r"(b0), "r"(b1));
}

// ---------------------------------------------------------------------------
// TF32 GEMM: out[M,N] = act(A[M,K] @ W[N,K]^T + bias) + res
// BM=128, BN in {96,48}. 8 warps; warp tile 32 x (BN/2).
// M%128==0, K%16==0. ACT: 0=none, 1=gelu.
// ---------------------------------------------------------------------------
template <int BN, int ACT, bool HASB, bool HASR>
__global__ __launch_bounds__(256) void gemm_tf32_kernel(
    const float* __restrict__ A, const float* __restrict__ W,
    const float* __restrict__ bias, const float* __restrict__ res,
    float* __restrict__ out, int M, int N, int K)
{
    constexpr int NF = BN / 16;         // n-frags per warp (96->6, 48->3)
    constexpr int SW = BN + 8;
    __shared__ unsigned As[2][16][136];
    __shared__ unsigned Ws[2][16][SW];

    int tid = threadIdx.x, lane = tid & 31, warp = tid >> 5;
    int wm = warp >> 1, wn = warp & 1;
    int qr = lane >> 2, qc = lane & 3;
    int m0 = blockIdx.x * 128, n0 = blockIdx.y * BN;

    float acc[2][NF][4];
#pragma unroll
    for (int i = 0; i < 2; i++)
#pragma unroll
        for (int j = 0; j < NF; j++)
#pragma unroll
            for (int q = 0; q < 4; q++) acc[i][j][q] = 0.f;

    float4 pa[2], pw[2];
    const int fA0 = tid, fA1 = tid + 256;
    const int mA0 = fA0 & 127, qA0 = fA0 >> 7;
    const int mA1 = fA1 & 127, qA1 = fA1 >> 7;
    const int fW1 = tid + 256;
    const int nW0 = tid % BN, qW0 = tid / BN;
    const int nW1 = fW1 % BN, qW1 = fW1 / BN;
    const bool hasW0 = (tid < BN * 4);
    const bool hasW1 = (fW1 < BN * 4);

    const int nk = K / 16;

    // ---- prologue: load + store tile 0 ----
    {
        pa[0] = *(const float4*)&A[(size_t)(m0 + mA0) * K + qA0 * 4];
        pa[1] = *(const float4*)&A[(size_t)(m0 + mA1) * K + qA1 * 4];
        if (hasW0) {
            float4 v = make_float4(0.f,0.f,0.f,0.f);
            if (n0 + nW0 < N) v = *(const float4*)&W[(size_t)(n0 + nW0) * K + qW0 * 4];
            pw[0] = v;
        }
        if (hasW1) {
            float4 v = make_float4(0.f,0.f,0.f,0.f);
            if (n0 + nW1 < N) v = *(const float4*)&W[(size_t)(n0 + nW1) * K + qW1 * 4];
            pw[1] = v;
        }
        As[0][qA0*4+0][mA0] = f2tf(pa[0].x); As[0][qA0*4+1][mA0] = f2tf(pa[0].y);
        As[0][qA0*4+2][mA0] = f2tf(pa[0].z); As[0][qA0*4+3][mA0] = f2tf(pa[0].w);
        As[0][qA1*4+0][mA1] = f2tf(pa[1].x); As[0][qA1*4+1][mA1] = f2tf(pa[1].y);
        As[0][qA1*4+2][mA1] = f2tf(pa[1].z); As[0][qA1*4+3][mA1] = f2tf(pa[1].w);
        if (hasW0) {
            Ws[0][qW0*4+0][nW0] = f2tf(pw[0].x); Ws[0][qW0*4+1][nW0] = f2tf(pw[0].y);
            Ws[0][qW0*4+2][nW0] = f2tf(pw[0].z); Ws[0][qW0*4+3][nW0] = f2tf(pw[0].w);
        }
        if (hasW1) {
            Ws[0][qW1*4+0][nW1] = f2tf(pw[1].x); Ws[0][qW1*4+1][nW1] = f2tf(pw[1].y);
            Ws[0][qW1*4+2][nW1] = f2tf(pw[1].z); Ws[0][qW1*4+3][nW1] = f2tf(pw[1].w);
        }
    }
    __syncthreads();

    for (int kt = 0; kt < nk; kt++) {
        int buf = kt & 1;
        bool more = (kt + 1 < nk);
        if (more) {
            int k0 = (kt + 1) * 16;
            pa[0] = *(const float4*)&A[(size_t)(m0 + mA0) * K + k0 + qA0 * 4];
            pa[1] = *(const float4*)&A[(size_t)(m0 + mA1) * K + k0 + qA1 * 4];
            if (hasW0) {
                float4 v = make_float4(0.f,0.f,0.f,0.f);
                if (n0 + nW0 < N) v = *(const float4*)&W[(size_t)(n0 + nW0) * K + k0 + qW0 * 4];
                pw[0] = v;
            }
            if (hasW1) {
                float4 v = make_float4(0.f,0.f,0.f,0.f);
                if (n0 + nW1 < N) v = *(const float4*)&W[(size_t)(n0 + nW1) * K + k0 + qW1 * 4];
                pw[1] = v;
            }
        }

        // compute on buf
#pragma unroll
        for (int ks = 0; ks < 2; ks++) {
            int kb = ks * 8;
            unsigned a[2][4];
#pragma unroll
            for (int mt = 0; mt < 2; mt++) {
                int r = wm * 32 + mt * 16 + qr;
                a[mt][0] = As[buf][kb + qc][r];
                a[mt][1] = As[buf][kb + qc][r + 8];
                a[mt][2] = As[buf][kb + qc + 4][r];
                a[mt][3] = As[buf][kb + qc + 4][r + 8];
            }
#pragma unroll
            for (int nt = 0; nt < NF; nt++) {
                int cn = wn * (NF * 8) + nt * 8 + qr;
                unsigned b0 = Ws[buf][kb + qc][cn];
                unsigned b1 = Ws[buf][kb + qc + 4][cn];
                mma8(acc[0][nt], a[0], b0, b1);
                mma8(acc[1][nt], a[1], b0, b1);
            }
        }

        if (more) {
            int nb = buf ^ 1;
            As[nb][qA0*4+0][mA0] = f2tf(pa[0].x); As[nb][qA0*4+1][mA0] = f2tf(pa[0].y);
            As[nb][qA0*4+2][mA0] = f2tf(pa[0].z); As[nb][qA0*4+3][mA0] = f2tf(pa[0].w);
            As[nb][qA1*4+0][mA1] = f2tf(pa[1].x); As[nb][qA1*4+1][mA1] = f2tf(pa[1].y);
            As[nb][qA1*4+2][mA1] = f2tf(pa[1].z); As[nb][qA1*4+3][mA1] = f2tf(pa[1].w);
            if (hasW0) {
                Ws[nb][qW0*4+0][nW0] = f2tf(pw[0].x); Ws[nb][qW0*4+1][nW0] = f2tf(pw[0].y);
                Ws[nb][qW0*4+2][nW0] = f2tf(pw[0].z); Ws[nb][qW0*4+3][nW0] = f2tf(pw[0].w);
            }
            if (hasW1) {
                Ws[nb][qW1*4+0][nW1] = f2tf(pw[1].x); Ws[nb][qW1*4+1][nW1] = f2tf(pw[1].y);
                Ws[nb][qW1*4+2][nW1] = f2tf(pw[1].z); Ws[nb][qW1*4+3][nW1] = f2tf(pw[1].w);
            }
            __syncthreads();
        }
    }

    // epilogue
#pragma unroll
    for (int mt = 0; mt < 2; mt++) {
        int r = m0 + wm * 32 + mt * 16 + qr;
#pragma unroll
        for (int nt = 0; nt < NF; nt++) {
            int c = n0 + wn * (NF * 8) + nt * 8 + 2 * qc;
            if (c >= N) continue;
            bool two = (c + 1 < N);
            float b0v = HASB ? bias[c] : 0.f;
            float b1v = (HASB && two) ? bias[c + 1] : 0.f;
            size_t ro0 = (size_t)r * N, ro1 = (size_t)(r + 8) * N;
            float v00 = acc[mt][nt][0] + b0v;
            float v01 = acc[mt][nt][1] + b1v;
            float v10 = acc[mt][nt][2] + b0v;
            float v11 = acc[mt][nt][3] + b1v;
            if (ACT == 1) { v00 = geluf(v00); v01 = geluf(v01);
                            v10 = geluf(v10); v11 = geluf(v11); }
            if (HASR) {
                v00 += res[ro0 + c]; v10 += res[ro1 + c];
                if (two) { v01 += res[ro0 + c + 1]; v11 += res[ro1 + c + 1]; }
            }
            out[ro0 + c] = v00;
            out[ro1 + c] = v10;
            if (two) { out[ro0 + c + 1] = v01; out[ro1 + c + 1] = v11; }
        }
    }
}

// ---------------------------------------------------------------------------
// Conv 1x3 over the N dim via tf32 MMA (3 shifted-A matmuls). Both directions
// in one launch: dir = blockIdx.x >> 8.
// ---------------------------------------------------------------------------
__global__ __launch_bounds__(256) void conv13_mma_kernel(
    const float* __restrict__ x,
    const float* __restrict__ w0, const float* __restrict__ b0,
    const float* __restrict__ w1, const float* __restrict__ b1)
{
    int dir = blockIdx.x >> 8;
    int bi  = blockIdx.x & 255;
    const float* w    = dir ? w1 : w0;
    const float* bias = dir ? b1 : b0;

    int bm = bi >> 3;                  // b*16 + m  (0..31)
    int n0 = (bi & 7) << 7;            // n tile start (0..896)
    int b  = bm >> 4, m_img = bm & 15;

    __shared__ unsigned As[16][136];       // As[cin][p], p = n-n0+1 (130 used)
    __shared__ unsigned Ws3[3][16][104];   // Ws3[tap][cin][cout]

    int tid = threadIdx.x, lane = tid & 31, warp = tid >> 5;
    int wm = warp >> 1, wn = warp & 1;
    int qr = lane >> 2, qc = lane & 3;

    float acc[2][6][4];
#pragma unroll
    for (int i = 0; i < 2; i++)
#pragma unroll
        for (int j = 0; j < 6; j++)
#pragma unroll
            for (int q = 0; q < 4; q++) acc[i][j][q] = 0.f;

    const float* xrow = x + (size_t)bm * 1024 * CCH;

    for (int c0 = 0; c0 < CCH; c0 += 16) {
        for (int f = tid; f < 520; f += 256) {
            int q = f / 130, p = f - q * 130;
            int n = n0 - 1 + p;
            float4 v = make_float4(0.f, 0.f, 0.f, 0.f);
            if (n >= 0 && n < 1024)
                v = *(const float4*)&xrow[(size_t)n * CCH + c0 + q * 4];
            As[q*4+0][p] = f2tf(v.x); As[q*4+1][p] = f2tf(v.y);
            As[q*4+2][p] = f2tf(v.z); As[q*4+3][p] = f2tf(v.w);
        }
        for (int f = tid; f < 4608; f += 256) {
            int tap = f / 1536, r = f - tap * 1536;
            int k = r / 96, cout = r - k * 96;
            Ws3[tap][k][cout] =
                f2tf(w[((size_t)cout * CCH + (c0 + k)) * 3 + tap]);
        }
        __syncthreads();

#pragma unroll
        for (int ks = 0; ks < 2; ks++) {
            int kb = ks * 8;
#pragma unroll
            for (int tap = 0; tap < 3; tap++) {
                int off = dir ? (1 - tap) : (tap - 1);
                unsigned a[2][4];
#pragma unroll
                for (int mt = 0; mt < 2; mt++) {
                    int r = wm * 32 + mt * 16 + qr + 1 + off;
                    a[mt][0] = As[kb + qc][r];
                    a[mt][1] = As[kb + qc][r + 8];
                    a[mt][2] = As[kb + qc + 4][r];
                    a[mt][3] = As[kb + qc + 4][r + 8];
                }
#pragma unroll
                for (int nt = 0; nt < 6; nt++) {
                    int cn = wn * 48 + nt * 8 + qr;
                    unsigned bb0 = Ws3[tap][kb + qc][cn];
                    unsigned bb1 = Ws3[tap][kb + qc + 4][cn];
                    mma8(acc[0][nt], a[0], bb0, bb1);
                    mma8(acc[1][nt], a[1], bb0, bb1);
                }
            }
        }
        __syncthreads();
    }

    int seq = dir * 2 + b;
    size_t lbase = (size_t)seq * TSEQ + (size_t)m_img * 1024 + n0;
#pragma unroll
    for (int mt = 0; mt < 2; mt++) {
        int tr = wm * 32 + mt * 16 + qr;
        size_t ro0 = (lbase + tr) * CCH;
        size_t ro1 = (lbase + tr + 8) * CCH;
#pragma unroll
        for (int nt = 0; nt < 6; nt++) {
            int c = wn * 48 + nt * 8 + 2 * qc;
            float bc0 = bias[c], bc1 = bias[c + 1];
            float2 s0 = make_float2(acc[mt][nt][0] + bc0, acc[mt][nt][1] + bc1);
            float2 s1 = make_float2(acc[mt][nt][2] + bc0, acc[mt][nt][3] + bc1);
            *(float2*)&g_cbuf[ro0 + c] = s0;
            *(float2*)&g_cbuf[ro1 + c] = s1;
        }
    }
}

// ---------------------------------------------------------------------------
// LayerNorm over 96 channels, warp per row. 256 thr = 8 rows/block.
// ---------------------------------------------------------------------------
__global__ __launch_bounds__(256) void ln_kernel(
    const float* __restrict__ in, float* __restrict__ out,
    const float* __restrict__ g, const float* __restrict__ bta, int rows)
{
    int row = blockIdx.x * 8 + (threadIdx.x >> 5);
    if (row >= rows) return;
    int lane = threadIdx.x & 31;
    const float* r = in + (size_t)row * CCH;
    float v0 = r[lane], v1 = r[lane+32], v2 = r[lane+64];
    float s = v0 + v1 + v2;
#pragma unroll
    for (int off = 16; off; off >>= 1) s += __shfl_xor_sync(0xffffffffu, s, off);
    float mu = s * (1.f/96.f);
    float d0 = v0-mu, d1 = v1-mu, d2 = v2-mu;
    float q = d0*d0 + d1*d1 + d2*d2;
#pragma unroll
    for (int off = 16; off; off >>= 1) q += __shfl_xor_sync(0xffffffffu, q, off);
    float rs = rsqrtf(q * (1.f/96.f) + 1e-5f);
    float* o = out + (size_t)row * CCH;
    o[lane]    = d0 * rs * g[lane]    + bta[lane];
    o[lane+32] = d1 * rs * g[lane+32] + bta[lane+32];
    o[lane+64] = d2 * rs * g[lane+64] + bta[lane+64];
}

// ---------------------------------------------------------------------------
// Fused combine + LayerNorm:
// ssm = mo[t] + mo[t+32768] + tcat[t] + tcat[t+32768]  -> g_outssm
// lnbuf = LN(ssm)                                       -> g_lnbuf
// ---------------------------------------------------------------------------
__global__ __launch_bounds__(256) void combine_ln_kernel(
    const float* __restrict__ g, const float* __restrict__ bta)
{
    int row = blockIdx.x * 8 + (threadIdx.x >> 5);
    int lane = threadIdx.x & 31;
    size_t lo = (size_t)row * CCH;
    size_t hi = lo + (size_t)TOK2 * CCH;
    float v0 = g_mo[lo+lane]    + g_mo[hi+lane]    + g_tcat[lo+lane]    + g_tcat[hi+lane];
    float v1 = g_mo[lo+lane+32] + g_mo[hi+lane+32] + g_tcat[lo+lane+32] + g_tcat[hi+lane+32];
    float v2 = g_mo[lo+lane+64] + g_mo[hi+lane+64] + g_tcat[lo+lane+64] + g_tcat[hi+lane+64];
    g_outssm[lo+lane]    = v0;
    g_outssm[lo+lane+32] = v1;
    g_outssm[lo+lane+64] = v2;
    float s = v0 + v1 + v2;
#pragma unroll
    for (int off = 16; off; off >>= 1) s += __shfl_xor_sync(0xffffffffu, s, off);
    float mu = s * (1.f/96.f);
    float d0 = v0-mu, d1 = v1-mu, d2 = v2-mu;
    float q = d0*d0 + d1*d1 + d2*d2;
#pragma unroll
    for (int off = 16; off; off >>= 1) q += __shfl_xor_sync(0xffffffffu, q, off);
    float rs = rsqrtf(q * (1.f/96.f) + 1e-5f);
    g_lnbuf[lo+lane]    = d0 * rs * g[lane]    + bta[lane];
    g_lnbuf[lo+lane+32] = d1 * rs * g[lane+32] + bta[lane+32];
    g_lnbuf[lo+lane+64] = d2 * rs * g[lane+64] + bta[lane+64];
}

// ---------------------------------------------------------------------------
// Depthwise causal conv1d (k=4) + bias + silu.
// One thread = 4 channels x 4 consecutive tokens; 7 row-loads in registers,
// sliding-window reuse. grid*block = (TTOK/4)*48.
// ---------------------------------------------------------------------------
__global__ __launch_bounds__(256) void conv1d_kernel(
    const float* __restrict__ xz, const float* __restrict__ w,
    const float* __restrict__ b)
{
    int idx = blockIdx.x * 256 + threadIdx.x;     // tokgrp*48 + d4
    int tg = idx / 48, d4 = idx - tg * 48;
    int d = d4 * 4;
    int t0 = tg * 4;
    int pos0 = t0 & (TSEQ - 1);

    float4 w0 = *(const float4*)&w[(d+0)*4];
    float4 w1 = *(const float4*)&w[(d+1)*4];
    float4 w2 = *(const float4*)&w[(d+2)*4];
    float4 w3 = *(const float4*)&w[(d+3)*4];
    float4 bv = *(const float4*)&b[d];

    float4 r[7];
#pragma unroll
    for (int k = 0; k < 7; k++) {
        int rel = k - 3;
        float4 v = make_float4(0.f, 0.f, 0.f, 0.f);
        if (pos0 + rel >= 0)   // only rows 0..2 at sequence start are zero-padded
            v = *(const float4*)&xz[(size_t)(t0 + rel) * 384 + d];
        r[k] = v;
    }

#pragma unroll
    for (int i = 0; i < 4; i++) {
        float4 acc = bv;
#pragma unroll
        for (int t = 0; t < 4; t++) {
            float4 xv = r[i + t];
            acc.x = fmaf(((const float*)&w0)[t], xv.x, acc.x);
            acc.y = fmaf(((const float*)&w1)[t], xv.y, acc.y);
            acc.z = fmaf(((const float*)&w2)[t], xv.z, acc.z);
            acc.w = fmaf(((const float*)&w3)[t], xv.w, acc.w);
        }
        float4 o;
        o.x = siluf(acc.x); o.y = siluf(acc.y);
        o.z = siluf(acc.z); o.w = siluf(acc.w);
        *(float4*)&g_xc[(size_t)(t0 + i) * DI + d] = o;
    }
}

// ---------------------------------------------------------------------------
// dt = softplus(x_dbl[:, :6] @ dt_proj_w^T + dt_proj_b); weights staged in smem.
// One thread = 1 token x 4 d's.
// ---------------------------------------------------------------------------
__global__ __launch_bounds__(256) void dt_kernel(
    const float* __restrict__ dtw, const float* __restrict__ dtb)
{
    __shared__ float ws[DI*DTR];
    __shared__ float bs[DI];
    int tid = threadIdx.x;
    for (int f = tid; f < DI*DTR; f += 256) ws[f] = dtw[f];
    for (int f = tid; f < DI; f += 256) bs[f] = dtb[f];
    __syncthreads();

    int idx = blockIdx.x * 256 + tid;     // tok*48 + d4
    int tok = idx / 48, d4 = idx - tok * 48;
    int d = d4 * 4;

    const float* xr = &g_xdbl[(size_t)tok * NXD];
    float x0 = xr[0], x1 = xr[1], x2 = xr[2];
    float x3 = xr[3], x4 = xr[4], x5 = xr[5];

    float4 o;
#pragma unroll
    for (int j = 0; j < 4; j++) {
        const float* wr = &ws[(d + j) * DTR];
        float acc = bs[d + j];
        acc = fmaf(wr[0], x0, acc); acc = fmaf(wr[1], x1, acc);
        acc = fmaf(wr[2], x2, acc); acc = fmaf(wr[3], x3, acc);
        acc = fmaf(wr[4], x4, acc); acc = fmaf(wr[5], x5, acc);
        ((float*)&o)[j] = softplusf(acc);
    }
    *(float4*)&g_dt[(size_t)tok * DI + d] = o;
}

// ---------------------------------------------------------------------------
// Scan S1: per (seq,chunk) block of 192 threads (one per d).
// ---------------------------------------------------------------------------
__global__ __launch_bounds__(192) void scan1_kernel(const float* __restrict__ A_log)
{
    int seq = blockIdx.x >> 7, ch = blockIdx.x & 127;
    int d = threadIdx.x;
    int tok0 = seq * TSEQ + ch * LCH;

    __shared__ __align__(16) float Bs[LCH][DS];
    for (int f = d; f < LCH*DS; f += 192) {
        int l = f >> 4, s = f & 15;
        Bs[l][s] = g_xdbl[(size_t)(tok0 + l) * NXD + DTR + s];
    }
    __syncthreads();

    float aa[DS], h[DS];
#pragma unroll
    for (int s = 0; s < DS; s++) {
        aa[s] = -expf(A_log[d*DS + s]) * LOG2E;
        h[s] = 0.f;
    }
    float dtsum = 0.f;

    for (int l = 0; l < LCH; l++) {
        int tok = tok0 + l;
        float dt = g_dt[(size_t)tok * DI + d];
        float u  = g_xc[(size_t)tok * DI + d];
        float du = dt * u;
        dtsum += dt;
        float bl[DS];
#pragma unroll
        for (int q = 0; q < 4; q++) {
            float4 v = *(const float4*)&Bs[l][q*4];
            bl[q*4]=v.x; bl[q*4+1]=v.y; bl[q*4+2]=v.z; bl[q*4+3]=v.w;
        }
#pragma unroll
        for (int s = 0; s < DS; s++) {
            float e = ex2f(aa[s] * dt);
            h[s] = fmaf(e, h[s], du * bl[s]);
        }
    }
    size_t base = ((size_t)(seq*NCH + ch) * DI + d) * DS;
#pragma unroll
    for (int s = 0; s < DS; s++) {
        g_hend[base + s] = h[s];
        g_P[base + s]    = ex2f(aa[s] * dtsum);
    }
}

// ---------------------------------------------------------------------------
// Scan S2: sequential cross-chunk combine; thread per (seq,d,s).
// ---------------------------------------------------------------------------
__global__ __launch_bounds__(256) void scan2_kernel()
{
    int idx = blockIdx.x * 256 + threadIdx.x;     // seq*3072 + d*16 + s
    int seq = idx / (DI*DS), ds_ = idx - seq * (DI*DS);
    float H = 0.f;
#pragma unroll 4
    for (int c = 0; c < NCH; c++) {
        size_t base = (size_t)(seq*NCH + c) * (DI*DS) + ds_;
        g_h0[base] = H;
        H = fmaf(g_P[base], H, g_hend[base]);
    }
}

// ---------------------------------------------------------------------------
// Scan S3: recompute local scan with initial state h0, emit
// yg = (y + u*Dp) * silu(z)  into g_y.
// ---------------------------------------------------------------------------
__global__ __launch_bounds__(192) void scan3_kernel(
    const float* __restrict__ A_log, const float* __restrict__ Dp)
{
    int seq = blockIdx.x >> 7, ch = blockIdx.x & 127;
    int d = threadIdx.x;
    int tok0 = seq * TSEQ + ch * LCH;

    __shared__ __align__(16) float Bs[LCH][DS];
    __shared__ __align__(16) float Cs[LCH][DS];
    for (int f = d; f < LCH*DS; f += 192) {
        int l = f >> 4, s = f & 15;
        size_t r = (size_t)(tok0 + l) * NXD + DTR;
        Bs[l][s] = g_xdbl[r + s];
        Cs[l][s] = g_xdbl[r + DS + s];
    }
    __syncthreads();

    float aa[DS], h[DS];
    size_t base = ((size_t)(seq*NCH + ch) * DI + d) * DS;
#pragma unroll
    for (int s = 0; s < DS; s++) {
        aa[s] = -expf(A_log[d*DS + s]) * LOG2E;
        h[s] = g_h0[base + s];
    }
    float dval = Dp[d];

    for (int l = 0; l < LCH; l++) {
        int tok = tok0 + l;
        float dt = g_dt[(size_t)tok * DI + d];
        float u  = g_xc[(size_t)tok * DI + d];
        float du = dt * u;
        float bl[DS], cl[DS];
#pragma unroll
        for (int q = 0; q < 4; q++) {
            float4 v = *(const float4*)&Bs[l][q*4];
            bl[q*4]=v.x; bl[q*4+1]=v.y; bl[q*4+2]=v.z; bl[q*4+3]=v.w;
            float4 c = *(const float4*)&Cs[l][q*4];
            cl[q*4]=c.x; cl[q*4+1]=c.y; cl[q*4+2]=c.z; cl[q*4+3]=c.w;
        }
        float y = 0.f;
#pragma unroll
        for (int s = 0; s < DS; s++) {
            float e = ex2f(aa[s] * dt);
            h[s] = fmaf(e, h[s], du * bl[s]);
            y = fmaf(h[s], cl[s], y);
        }
        y = fmaf(u, dval, y);
        float z = g_xz[(size_t)tok * 384 + DI + d];
        g_y[(size_t)tok * DI + d] = y * siluf(z);
    }
}

// ---------------------------------------------------------------------------
extern "C" void kernel_launch(void* const* d_in, const int* in_sizes, int n_in,
                              void* d_out, int out_size) {
    const float* x          = (const float*)d_in[0];
    const float* conv1234_w = (const float*)d_in[1];
    const float* conv1234_b = (const float*)d_in[2];
    const float* conv4321_w = (const float*)d_in[3];
    const float* conv4321_b = (const float*)d_in[4];
    const float* ln_g       = (const float*)d_in[5];
    const float* ln_b       = (const float*)d_in[6];
    const float* in_proj_w  = (const float*)d_in[7];
    const float* conv1d_w   = (const float*)d_in[8];
    const float* conv1d_b   = (const float*)d_in[9];
    const float* x_proj_w   = (const float*)d_in[10];
    const float* dt_proj_w  = (const float*)d_in[11];
    const float* dt_proj_b  = (const float*)d_in[12];
    const float* A_log      = (const float*)d_in[13];
    const float* Dp         = (const float*)d_in[14];
    const float* out_proj_w = (const float*)d_in[15];
    const float* fc1_w      = (const float*)d_in[16];
    const float* fc1_b      = (const float*)d_in[17];
    const float* fc2_w      = (const float*)d_in[18];
    const float* fc2_b      = (const float*)d_in[19];
    float* out = (float*)d_out;

    float *cbuf, *tcat, *xz, *xc, *xdbl, *y, *mo, *outssm, *lnbuf, *mid;
    cudaGetSymbolAddress((void**)&cbuf,   g_cbuf);
    cudaGetSymbolAddress((void**)&tcat,   g_tcat);
    cudaGetSymbolAddress((void**)&xz,     g_xz);
    cudaGetSymbolAddress((void**)&xc,     g_xc);
    cudaGetSymbolAddress((void**)&xdbl,   g_xdbl);
    cudaGetSymbolAddress((void**)&y,      g_y);
    cudaGetSymbolAddress((void**)&mo,     g_mo);
    cudaGetSymbolAddress((void**)&outssm, g_outssm);
    cudaGetSymbolAddress((void**)&lnbuf,  g_lnbuf);
    cudaGetSymbolAddress((void**)&mid,    g_mid);

    // 1) conv 1x3 both directions (one launch) -> g_cbuf [4 seqs][16384][96]
    conv13_mma_kernel<<<512, 256>>>(x, conv1234_w, conv1234_b,
                                    conv4321_w, conv4321_b);

    // 2) LN -> g_tcat (t1 stacked with t2, 65536 rows)
    ln_kernel<<<TTOK/8, 256>>>(cbuf, tcat, ln_g, ln_b, TTOK);

    // 3) in_proj: [65536,96] @ [384,96]^T -> g_xz
    {
        dim3 grid(TTOK/128, 4);
        gemm_tf32_kernel<96,0,false,false><<<grid, 256>>>(tcat, in_proj_w, nullptr, nullptr, xz, TTOK, 384, CCH);
    }

    // 4) depthwise conv1d + silu -> g_xc (4 tokens x 4 ch per thread)
    conv1d_kernel<<<(TTOK/4*48)/256, 256>>>(xz, conv1d_w, conv1d_b);

    // 5) x_proj: [65536,192] @ [38,192]^T -> g_xdbl  (BN=48 tile)
    {
        dim3 grid(TTOK/128, 1);
        gemm_tf32_kernel<48,0,false,false><<<grid, 256>>>(xc, x_proj_w, nullptr, nullptr, xdbl, TTOK, NXD, DI);
    }

    // 6) dt projection + softplus -> g_dt (smem weights)
    dt_kernel<<<(TTOK*48)/256, 256>>>(dt_proj_w, dt_proj_b);

    // 7-9) chunked selective scan
    scan1_kernel<<<NSEQ*NCH, 192>>>(A_log);
    scan2_kernel<<<(NSEQ*DI*DS)/256, 256>>>();
    scan3_kernel<<<NSEQ*NCH, 192>>>(A_log, Dp);

    // 10) out_proj: [65536,192] @ [96,192]^T -> g_mo
    {
        dim3 grid(TTOK/128, 1);
        gemm_tf32_kernel<96,0,false,false><<<grid, 256>>>(y, out_proj_w, nullptr, nullptr, mo, TTOK, CCH, DI);
    }

    // 11+12) fused combine + LN -> g_outssm, g_lnbuf
    combine_ln_kernel<<<TOK2/8, 256>>>(ln_g, ln_b);

    // 13) fc1 + gelu -> g_mid
    {
        dim3 grid(TOK2/128, 1);
        gemm_tf32_kernel<96,1,true,false><<<grid, 256>>>(lnbuf, fc1_w, fc1_b, nullptr, mid, TOK2, CCH, CCH);
    }

    // 14) fc2 + bias + residual(out_ssm) -> d_out
    {
        dim3 grid(TOK2/128, 1);
        gemm_tf32_kernel<96,0,true,true><<<grid, 256>>>(mid, fc2_w, fc2_b, outssm, out, TOK2, CCH, CCH);
    }
}

// round 9
// speedup vs baseline: 1.1347x; 1.0180x over previous
#include <cuda_runtime.h>
#include <cuda_bf16.h>
#include <math.h>

// ---------------------------------------------------------------------------
// Problem constants
// ---------------------------------------------------------------------------
#define TSEQ 16384          // L per mamba sequence (M*N)
#define NSEQ 4              // 2 batches x 2 directions
#define TTOK 65536          // NSEQ*TSEQ
#define TOK2 32768          // output tokens (B*M*N)
#define CCH  96
#define DI   192
#define DS   16
#define NXD  38             // dtr(6) + 2*ds(32)
#define DTR  6
#define NCH  128            // scan chunks per sequence
#define LCH  128            // chunk length
#define LOG2E 1.4426950408889634f

// ---------------------------------------------------------------------------
// Scratch (static device globals; no allocation allowed)
// ---------------------------------------------------------------------------
static __device__ __align__(256) float g_tcat  [(size_t)TTOK*CCH];
static __device__ __align__(256) float g_xz    [(size_t)TTOK*384];
static __device__ __align__(256) float g_xc    [(size_t)TTOK*DI];
static __device__ __align__(256) float g_xdbl  [(size_t)TTOK*NXD];
static __device__ __align__(256) float g_dt    [(size_t)TTOK*DI];
static __device__ __align__(256) float g_y     [(size_t)TTOK*DI];
static __device__ __align__(256) float g_mo    [(size_t)TTOK*CCH];
static __device__ __align__(256) float g_outssm[(size_t)TOK2*CCH];
static __device__ __align__(256) float g_lnbuf [(size_t)TOK2*CCH];
static __device__ __align__(256) float g_mid   [(size_t)TOK2*CCH];
static __device__ __align__(256) float g_hend  [NSEQ*NCH*DI*DS];
static __device__ __align__(256) float g_P     [NSEQ*NCH*DI*DS];
static __device__ __align__(256) float g_h0    [NSEQ*NCH*DI*DS];

// ---------------------------------------------------------------------------
// helpers
// ---------------------------------------------------------------------------
__device__ __forceinline__ float ex2f(float x) {
    float y;
    asm("ex2.approx.f32 %0, %1;" : "=f"(y) : "f"(x));
    return y;
}
__device__ __forceinline__ float siluf(float x) {
    return x / (1.0f + expf(-x));
}
__device__ __forceinline__ float softplusf(float x) {
    return (x > 20.0f) ? x : log1pf(expf(x));
}
__device__ __forceinline__ float geluf(float x) {
    return 0.5f * x * (1.0f + erff(x * 0.7071067811865476f));
}
__device__ __forceinline__ unsigned f2tf(float x) {
    unsigned r;
    asm("cvt.rna.tf32.f32 %0, %1;" : "=r"(r) : "f"(x));
    return r;
}
// D += A(16x8,row) * B(8x8,col) tf32
__device__ __forceinline__ void mma8(float* c, const unsigned* a,
                                     unsigned b0, unsigned b1) {
    asm volatile(
        "mma.sync.aligned.m16n8k8.row.col.f32.tf32.tf32.f32 "
        "{%0,%1,%2,%3}, {%4,%5,%6,%7}, {%8,%9}, {%0,%1,%2,%3};"
        : "+f"(c[0]), "+f"(c[1]), "+f"(c[2]), "+f"(c[3])
        : "r"(a[0]), "r"(a[1]), "r"(a[2]), "r"(a[3]), "r"(b0), "r"(b1));
}

// ---------------------------------------------------------------------------
// TF32 GEMM: out[M,N] = act(A[M,K] @ W[N,K]^T + bias) + res
// BM=256, BN in {96,48}. 8 warps; warp tile 64 x (BN/2) (4 m-frags).
// M%256==0, K%16==0. ACT: 0=none, 1=gelu.
// A staging: one row per thread, full BK=16 in 4x float4 (conflict-free STS).
// ---------------------------------------------------------------------------
template <int BN, int ACT, bool HASB, bool HASR>
__global__ __launch_bounds__(256) void gemm_tf32_kernel(
    const float* __restrict__ A, const float* __restrict__ W,
    const float* __restrict__ bias, const float* __restrict__ res,
    float* __restrict__ out, int M, int N, int K)
{
    constexpr int NF = BN / 16;         // n-frags per warp (96->6, 48->3)
    constexpr int SW = BN + 8;
    __shared__ unsigned As[2][16][264];
    __shared__ unsigned Ws[2][16][SW];

    int tid = threadIdx.x, lane = tid & 31, warp = tid >> 5;
    int wm = warp >> 1, wn = warp & 1;
    int qr = lane >> 2, qc = lane & 3;
    int m0 = blockIdx.x * 256, n0 = blockIdx.y * BN;

    float acc[4][NF][4];
#pragma unroll
    for (int i = 0; i < 4; i++)
#pragma unroll
        for (int j = 0; j < NF; j++)
#pragma unroll
            for (int q = 0; q < 4; q++) acc[i][j][q] = 0.f;

    float4 pa[4], pw[2];
    const float* arow = &A[(size_t)(m0 + tid) * K];
    const int fW1 = tid + 256;
    const int nW0 = tid % BN, qW0 = tid / BN;
    const int nW1 = fW1 % BN, qW1 = fW1 / BN;
    const bool hasW0 = (tid < BN * 4);
    const bool hasW1 = (fW1 < BN * 4);

    const int nk = K / 16;

    // ---- prologue: load + store tile 0 ----
    {
#pragma unroll
        for (int it = 0; it < 4; it++)
            pa[it] = *(const float4*)&arow[it * 4];
        if (hasW0) {
            float4 v = make_float4(0.f,0.f,0.f,0.f);
            if (n0 + nW0 < N) v = *(const float4*)&W[(size_t)(n0 + nW0) * K + qW0 * 4];
            pw[0] = v;
        }
        if (hasW1) {
            float4 v = make_float4(0.f,0.f,0.f,0.f);
            if (n0 + nW1 < N) v = *(const float4*)&W[(size_t)(n0 + nW1) * K + qW1 * 4];
            pw[1] = v;
        }
#pragma unroll
        for (int it = 0; it < 4; it++) {
            As[0][it*4+0][tid] = f2tf(pa[it].x); As[0][it*4+1][tid] = f2tf(pa[it].y);
            As[0][it*4+2][tid] = f2tf(pa[it].z); As[0][it*4+3][tid] = f2tf(pa[it].w);
        }
        if (hasW0) {
            Ws[0][qW0*4+0][nW0] = f2tf(pw[0].x); Ws[0][qW0*4+1][nW0] = f2tf(pw[0].y);
            Ws[0][qW0*4+2][nW0] = f2tf(pw[0].z); Ws[0][qW0*4+3][nW0] = f2tf(pw[0].w);
        }
        if (hasW1) {
            Ws[0][qW1*4+0][nW1] = f2tf(pw[1].x); Ws[0][qW1*4+1][nW1] = f2tf(pw[1].y);
            Ws[0][qW1*4+2][nW1] = f2tf(pw[1].z); Ws[0][qW1*4+3][nW1] = f2tf(pw[1].w);
        }
    }
    __syncthreads();

    for (int kt = 0; kt < nk; kt++) {
        int buf = kt & 1;
        bool more = (kt + 1 < nk);
        if (more) {
            int k0 = (kt + 1) * 16;
#pragma unroll
            for (int it = 0; it < 4; it++)
                pa[it] = *(const float4*)&arow[k0 + it * 4];
            if (hasW0) {
                float4 v = make_float4(0.f,0.f,0.f,0.f);
                if (n0 + nW0 < N) v = *(const float4*)&W[(size_t)(n0 + nW0) * K + k0 + qW0 * 4];
                pw[0] = v;
            }
            if (hasW1) {
                float4 v = make_float4(0.f,0.f,0.f,0.f);
                if (n0 + nW1 < N) v = *(const float4*)&W[(size_t)(n0 + nW1) * K + k0 + qW1 * 4];
                pw[1] = v;
            }
        }

        // compute on buf: 2 ks-steps x (4 m-frags x NF n-frags)
#pragma unroll
        for (int ks = 0; ks < 2; ks++) {
            int kb = ks * 8;
            unsigned a[4][4];
#pragma unroll
            for (int mt = 0; mt < 4; mt++) {
                int r = wm * 64 + mt * 16 + qr;
                a[mt][0] = As[buf][kb + qc][r];
                a[mt][1] = As[buf][kb + qc][r + 8];
                a[mt][2] = As[buf][kb + qc + 4][r];
                a[mt][3] = As[buf][kb + qc + 4][r + 8];
            }
#pragma unroll
            for (int nt = 0; nt < NF; nt++) {
                int cn = wn * (NF * 8) + nt * 8 + qr;
                unsigned b0 = Ws[buf][kb + qc][cn];
                unsigned b1 = Ws[buf][kb + qc + 4][cn];
#pragma unroll
                for (int mt = 0; mt < 4; mt++)
                    mma8(acc[mt][nt], a[mt], b0, b1);
            }
        }

        if (more) {
            int nb = buf ^ 1;
#pragma unroll
            for (int it = 0; it < 4; it++) {
                As[nb][it*4+0][tid] = f2tf(pa[it].x); As[nb][it*4+1][tid] = f2tf(pa[it].y);
                As[nb][it*4+2][tid] = f2tf(pa[it].z); As[nb][it*4+3][tid] = f2tf(pa[it].w);
            }
            if (hasW0) {
                Ws[nb][qW0*4+0][nW0] = f2tf(pw[0].x); Ws[nb][qW0*4+1][nW0] = f2tf(pw[0].y);
                Ws[nb][qW0*4+2][nW0] = f2tf(pw[0].z); Ws[nb][qW0*4+3][nW0] = f2tf(pw[0].w);
            }
            if (hasW1) {
                Ws[nb][qW1*4+0][nW1] = f2tf(pw[1].x); Ws[nb][qW1*4+1][nW1] = f2tf(pw[1].y);
                Ws[nb][qW1*4+2][nW1] = f2tf(pw[1].z); Ws[nb][qW1*4+3][nW1] = f2tf(pw[1].w);
            }
            __syncthreads();
        }
    }

    // epilogue
#pragma unroll
    for (int mt = 0; mt < 4; mt++) {
        int r = m0 + wm * 64 + mt * 16 + qr;
#pragma unroll
        for (int nt = 0; nt < NF; nt++) {
            int c = n0 + wn * (NF * 8) + nt * 8 + 2 * qc;
            if (c >= N) continue;
            bool two = (c + 1 < N);
            float b0v = HASB ? bias[c] : 0.f;
            float b1v = (HASB && two) ? bias[c + 1] : 0.f;
            size_t ro0 = (size_t)r * N, ro1 = (size_t)(r + 8) * N;
            float v00 = acc[mt][nt][0] + b0v;
            float v01 = acc[mt][nt][1] + b1v;
            float v10 = acc[mt][nt][2] + b0v;
            float v11 = acc[mt][nt][3] + b1v;
            if (ACT == 1) { v00 = geluf(v00); v01 = geluf(v01);
                            v10 = geluf(v10); v11 = geluf(v11); }
            if (HASR) {
                v00 += res[ro0 + c]; v10 += res[ro1 + c];
                if (two) { v01 += res[ro0 + c + 1]; v11 += res[ro1 + c + 1]; }
            }
            out[ro0 + c] = v00;
            out[ro1 + c] = v10;
            if (two) { out[ro0 + c + 1] = v01; out[ro1 + c + 1] = v11; }
        }
    }
}

// ---------------------------------------------------------------------------
// Conv 1x3 (tf32 MMA, 3 shifted-A matmuls) FUSED with LayerNorm.
// Both directions in one launch: dir = blockIdx.x >> 8.
// The block tile is 128 positions x all 96 channels, so LN's reduction axis
// is block-resident: stage conv outputs in smem, warp-per-row reduce, and
// write post-LN values directly to g_tcat (g_cbuf eliminated).
// Dynamic smem: max(As+Ws3, lnbuf) = 50176 B (aliased; synced between uses).
// ---------------------------------------------------------------------------
__global__ __launch_bounds__(256) void conv13_ln_kernel(
    const float* __restrict__ x,
    const float* __restrict__ w0, const float* __restrict__ b0,
    const float* __restrict__ w1, const float* __restrict__ b1,
    const float* __restrict__ lng, const float* __restrict__ lnb)
{
    extern __shared__ unsigned char dynsm[];
    unsigned (*As)[136]      = reinterpret_cast<unsigned(*)[136]>(dynsm);
    unsigned (*Ws3)[16][104] = reinterpret_cast<unsigned(*)[16][104]>(dynsm + 16*136*4);

    int dir = blockIdx.x >> 8;
    int bi  = blockIdx.x & 255;
    const float* w    = dir ? w1 : w0;
    const float* bias = dir ? b1 : b0;

    int bm = bi >> 3;                  // b*16 + m  (0..31)
    int n0 = (bi & 7) << 7;            // n tile start (0..896)
    int b  = bm >> 4, m_img = bm & 15;

    int tid = threadIdx.x, lane = tid & 31, warp = tid >> 5;
    int wm = warp >> 1, wn = warp & 1;
    int qr = lane >> 2, qc = lane & 3;

    float acc[2][6][4];
#pragma unroll
    for (int i = 0; i < 2; i++)
#pragma unroll
        for (int j = 0; j < 6; j++)
#pragma unroll
            for (int q = 0; q < 4; q++) acc[i][j][q] = 0.f;

    const float* xrow = x + (size_t)bm * 1024 * CCH;

    for (int c0 = 0; c0 < CCH; c0 += 16) {
        for (int f = tid; f < 520; f += 256) {
            int q = f / 130, p = f - q * 130;
            int n = n0 - 1 + p;
            float4 v = make_float4(0.f, 0.f, 0.f, 0.f);
            if (n >= 0 && n < 1024)
                v = *(const float4*)&xrow[(size_t)n * CCH + c0 + q * 4];
            As[q*4+0][p] = f2tf(v.x); As[q*4+1][p] = f2tf(v.y);
            As[q*4+2][p] = f2tf(v.z); As[q*4+3][p] = f2tf(v.w);
        }
        for (int f = tid; f < 4608; f += 256) {
            int tap = f / 1536, r = f - tap * 1536;
            int k = r / 96, cout = r - k * 96;
            Ws3[tap][k][cout] =
                f2tf(w[((size_t)cout * CCH + (c0 + k)) * 3 + tap]);
        }
        __syncthreads();

#pragma unroll
        for (int ks = 0; ks < 2; ks++) {
            int kb = ks * 8;
#pragma unroll
            for (int tap = 0; tap < 3; tap++) {
                int off = dir ? (1 - tap) : (tap - 1);
                unsigned a[2][4];
#pragma unroll
                for (int mt = 0; mt < 2; mt++) {
                    int r = wm * 32 + mt * 16 + qr + 1 + off;
                    a[mt][0] = As[kb + qc][r];
                    a[mt][1] = As[kb + qc][r + 8];
                    a[mt][2] = As[kb + qc + 4][r];
                    a[mt][3] = As[kb + qc + 4][r + 8];
                }
#pragma unroll
                for (int nt = 0; nt < 6; nt++) {
                    int cn = wn * 48 + nt * 8 + qr;
                    unsigned bb0 = Ws3[tap][kb + qc][cn];
                    unsigned bb1 = Ws3[tap][kb + qc + 4][cn];
                    mma8(acc[0][nt], a[0], bb0, bb1);
                    mma8(acc[1][nt], a[1], bb0, bb1);
                }
            }
        }
        __syncthreads();
    }

    // ---- fused LN epilogue ----
    float (*lnbuf)[98] = reinterpret_cast<float(*)[98]>(dynsm);  // aliases As/Ws3
    // (last __syncthreads above guarantees no warp is still reading As/Ws3)
#pragma unroll
    for (int mt = 0; mt < 2; mt++) {
        int tr = wm * 32 + mt * 16 + qr;
#pragma unroll
        for (int nt = 0; nt < 6; nt++) {
            int c = wn * 48 + nt * 8 + 2 * qc;
            float bc0 = bias[c], bc1 = bias[c + 1];
            lnbuf[tr][c]       = acc[mt][nt][0] + bc0;
            lnbuf[tr][c + 1]   = acc[mt][nt][1] + bc1;
            lnbuf[tr + 8][c]     = acc[mt][nt][2] + bc0;
            lnbuf[tr + 8][c + 1] = acc[mt][nt][3] + bc1;
        }
    }
    __syncthreads();

    int seq = dir * 2 + b;
    size_t lbase = (size_t)seq * TSEQ + (size_t)m_img * 1024 + n0;
    float gg0 = lng[lane], gg1 = lng[lane+32], gg2 = lng[lane+64];
    float bb0 = lnb[lane], bb1 = lnb[lane+32], bb2 = lnb[lane+64];
#pragma unroll
    for (int rr = 0; rr < 16; rr++) {
        int row = warp * 16 + rr;
        float v0 = lnbuf[row][lane], v1 = lnbuf[row][lane+32], v2 = lnbuf[row][lane+64];
        float s = v0 + v1 + v2;
#pragma unroll
        for (int off = 16; off; off >>= 1) s += __shfl_xor_sync(0xffffffffu, s, off);
        float mu = s * (1.f/96.f);
        float d0 = v0-mu, d1 = v1-mu, d2 = v2-mu;
        float q = d0*d0 + d1*d1 + d2*d2;
#pragma unroll
        for (int off = 16; off; off >>= 1) q += __shfl_xor_sync(0xffffffffu, q, off);
        float rs = rsqrtf(q * (1.f/96.f) + 1e-5f);
        float* o = &g_tcat[(lbase + row) * CCH];
        o[lane]    = d0 * rs * gg0 + bb0;
        o[lane+32] = d1 * rs * gg1 + bb1;
        o[lane+64] = d2 * rs * gg2 + bb2;
    }
}

// ---------------------------------------------------------------------------
// Fused combine + LayerNorm:
// ssm = mo[t] + mo[t+32768] + tcat[t] + tcat[t+32768]  -> g_outssm
// lnbuf = LN(ssm)                                       -> g_lnbuf
// ---------------------------------------------------------------------------
__global__ __launch_bounds__(256) void combine_ln_kernel(
    const float* __restrict__ g, const float* __restrict__ bta)
{
    int row = blockIdx.x * 8 + (threadIdx.x >> 5);
    int lane = threadIdx.x & 31;
    size_t lo = (size_t)row * CCH;
    size_t hi = lo + (size_t)TOK2 * CCH;
    float v0 = g_mo[lo+lane]    + g_mo[hi+lane]    + g_tcat[lo+lane]    + g_tcat[hi+lane];
    float v1 = g_mo[lo+lane+32] + g_mo[hi+lane+32] + g_tcat[lo+lane+32] + g_tcat[hi+lane+32];
    float v2 = g_mo[lo+lane+64] + g_mo[hi+lane+64] + g_tcat[lo+lane+64] + g_tcat[hi+lane+64];
    g_outssm[lo+lane]    = v0;
    g_outssm[lo+lane+32] = v1;
    g_outssm[lo+lane+64] = v2;
    float s = v0 + v1 + v2;
#pragma unroll
    for (int off = 16; off; off >>= 1) s += __shfl_xor_sync(0xffffffffu, s, off);
    float mu = s * (1.f/96.f);
    float d0 = v0-mu, d1 = v1-mu, d2 = v2-mu;
    float q = d0*d0 + d1*d1 + d2*d2;
#pragma unroll
    for (int off = 16; off; off >>= 1) q += __shfl_xor_sync(0xffffffffu, q, off);
    float rs = rsqrtf(q * (1.f/96.f) + 1e-5f);
    g_lnbuf[lo+lane]    = d0 * rs * g[lane]    + bta[lane];
    g_lnbuf[lo+lane+32] = d1 * rs * g[lane+32] + bta[lane+32];
    g_lnbuf[lo+lane+64] = d2 * rs * g[lane+64] + bta[lane+64];
}

// ---------------------------------------------------------------------------
// Depthwise causal conv1d (k=4) + bias + silu.
// One thread = 4 channels x 4 consecutive tokens; sliding-window registers.
// ---------------------------------------------------------------------------
__global__ __launch_bounds__(256) void conv1d_kernel(
    const float* __restrict__ xz, const float* __restrict__ w,
    const float* __restrict__ b)
{
    int idx = blockIdx.x * 256 + threadIdx.x;     // tokgrp*48 + d4
    int tg = idx / 48, d4 = idx - tg * 48;
    int d = d4 * 4;
    int t0 = tg * 4;
    int pos0 = t0 & (TSEQ - 1);

    float4 w0 = *(const float4*)&w[(d+0)*4];
    float4 w1 = *(const float4*)&w[(d+1)*4];
    float4 w2 = *(const float4*)&w[(d+2)*4];
    float4 w3 = *(const float4*)&w[(d+3)*4];
    float4 bv = *(const float4*)&b[d];

    float4 r[7];
#pragma unroll
    for (int k = 0; k < 7; k++) {
        int rel = k - 3;
        float4 v = make_float4(0.f, 0.f, 0.f, 0.f);
        if (pos0 + rel >= 0)
            v = *(const float4*)&xz[(size_t)(t0 + rel) * 384 + d];
        r[k] = v;
    }

#pragma unroll
    for (int i = 0; i < 4; i++) {
        float4 acc = bv;
#pragma unroll
        for (int t = 0; t < 4; t++) {
            float4 xv = r[i + t];
            acc.x = fmaf(((const float*)&w0)[t], xv.x, acc.x);
            acc.y = fmaf(((const float*)&w1)[t], xv.y, acc.y);
            acc.z = fmaf(((const float*)&w2)[t], xv.z, acc.z);
            acc.w = fmaf(((const float*)&w3)[t], xv.w, acc.w);
        }
        float4 o;
        o.x = siluf(acc.x); o.y = siluf(acc.y);
        o.z = siluf(acc.z); o.w = siluf(acc.w);
        *(float4*)&g_xc[(size_t)(t0 + i) * DI + d] = o;
    }
}

// ---------------------------------------------------------------------------
// dt = softplus(x_dbl[:, :6] @ dt_proj_w^T + dt_proj_b); weights in smem.
// ---------------------------------------------------------------------------
__global__ __launch_bounds__(256) void dt_kernel(
    const float* __restrict__ dtw, const float* __restrict__ dtb)
{
    __shared__ float ws[DI*DTR];
    __shared__ float bs[DI];
    int tid = threadIdx.x;
    for (int f = tid; f < DI*DTR; f += 256) ws[f] = dtw[f];
    for (int f = tid; f < DI; f += 256) bs[f] = dtb[f];
    __syncthreads();

    int idx = blockIdx.x * 256 + tid;     // tok*48 + d4
    int tok = idx / 48, d4 = idx - tok * 48;
    int d = d4 * 4;

    const float* xr = &g_xdbl[(size_t)tok * NXD];
    float x0 = xr[0], x1 = xr[1], x2 = xr[2];
    float x3 = xr[3], x4 = xr[4], x5 = xr[5];

    float4 o;
#pragma unroll
    for (int j = 0; j < 4; j++) {
        const float* wr = &ws[(d + j) * DTR];
        float acc = bs[d + j];
        acc = fmaf(wr[0], x0, acc); acc = fmaf(wr[1], x1, acc);
        acc = fmaf(wr[2], x2, acc); acc = fmaf(wr[3], x3, acc);
        acc = fmaf(wr[4], x4, acc); acc = fmaf(wr[5], x5, acc);
        ((float*)&o)[j] = softplusf(acc);
    }
    *(float4*)&g_dt[(size_t)tok * DI + d] = o;
}

// ---------------------------------------------------------------------------
// Scan S1: per (seq,chunk) block of 192 threads (one per d).
// ---------------------------------------------------------------------------
__global__ __launch_bounds__(192) void scan1_kernel(const float* __restrict__ A_log)
{
    int seq = blockIdx.x >> 7, ch = blockIdx.x & 127;
    int d = threadIdx.x;
    int tok0 = seq * TSEQ + ch * LCH;

    __shared__ __align__(16) float Bs[LCH][DS];
    for (int f = d; f < LCH*DS; f += 192) {
        int l = f >> 4, s = f & 15;
        Bs[l][s] = g_xdbl[(size_t)(tok0 + l) * NXD + DTR + s];
    }
    __syncthreads();

    float aa[DS], h[DS];
#pragma unroll
    for (int s = 0; s < DS; s++) {
        aa[s] = -expf(A_log[d*DS + s]) * LOG2E;
        h[s] = 0.f;
    }
    float dtsum = 0.f;

    for (int l = 0; l < LCH; l++) {
        int tok = tok0 + l;
        float dt = g_dt[(size_t)tok * DI + d];
        float u  = g_xc[(size_t)tok * DI + d];
        float du = dt * u;
        dtsum += dt;
        float bl[DS];
#pragma unroll
        for (int q = 0; q < 4; q++) {
            float4 v = *(const float4*)&Bs[l][q*4];
            bl[q*4]=v.x; bl[q*4+1]=v.y; bl[q*4+2]=v.z; bl[q*4+3]=v.w;
        }
#pragma unroll
        for (int s = 0; s < DS; s++) {
            float e = ex2f(aa[s] * dt);
            h[s] = fmaf(e, h[s], du * bl[s]);
        }
    }
    size_t base = ((size_t)(seq*NCH + ch) * DI + d) * DS;
#pragma unroll
    for (int s = 0; s < DS; s++) {
        g_hend[base + s] = h[s];
        g_P[base + s]    = ex2f(aa[s] * dtsum);
    }
}

// ---------------------------------------------------------------------------
// Scan S2: sequential cross-chunk combine; thread per (seq,d,s).
// ---------------------------------------------------------------------------
__global__ __launch_bounds__(256) void scan2_kernel()
{
    int idx = blockIdx.x * 256 + threadIdx.x;     // seq*3072 + d*16 + s
    int seq = idx / (DI*DS), ds_ = idx - seq * (DI*DS);
    float H = 0.f;
#pragma unroll 4
    for (int c = 0; c < NCH; c++) {
        size_t base = (size_t)(seq*NCH + c) * (DI*DS) + ds_;
        g_h0[base] = H;
        H = fmaf(g_P[base], H, g_hend[base]);
    }
}

// ---------------------------------------------------------------------------
// Scan S3: recompute local scan with initial state h0, emit
// yg = (y + u*Dp) * silu(z)  into g_y.
// ---------------------------------------------------------------------------
__global__ __launch_bounds__(192) void scan3_kernel(
    const float* __restrict__ A_log, const float* __restrict__ Dp)
{
    int seq = blockIdx.x >> 7, ch = blockIdx.x & 127;
    int d = threadIdx.x;
    int tok0 = seq * TSEQ + ch * LCH;

    __shared__ __align__(16) float Bs[LCH][DS];
    __shared__ __align__(16) float Cs[LCH][DS];
    for (int f = d; f < LCH*DS; f += 192) {
        int l = f >> 4, s = f & 15;
        size_t r = (size_t)(tok0 + l) * NXD + DTR;
        Bs[l][s] = g_xdbl[r + s];
        Cs[l][s] = g_xdbl[r + DS + s];
    }
    __syncthreads();

    float aa[DS], h[DS];
    size_t base = ((size_t)(seq*NCH + ch) * DI + d) * DS;
#pragma unroll
    for (int s = 0; s < DS; s++) {
        aa[s] = -expf(A_log[d*DS + s]) * LOG2E;
        h[s] = g_h0[base + s];
    }
    float dval = Dp[d];

    for (int l = 0; l < LCH; l++) {
        int tok = tok0 + l;
        float dt = g_dt[(size_t)tok * DI + d];
        float u  = g_xc[(size_t)tok * DI + d];
        float du = dt * u;
        float bl[DS], cl[DS];
#pragma unroll
        for (int q = 0; q < 4; q++) {
            float4 v = *(const float4*)&Bs[l][q*4];
            bl[q*4]=v.x; bl[q*4+1]=v.y; bl[q*4+2]=v.z; bl[q*4+3]=v.w;
            float4 c = *(const float4*)&Cs[l][q*4];
            cl[q*4]=c.x; cl[q*4+1]=c.y; cl[q*4+2]=c.z; cl[q*4+3]=c.w;
        }
        float y = 0.f;
#pragma unroll
        for (int s = 0; s < DS; s++) {
            float e = ex2f(aa[s] * dt);
            h[s] = fmaf(e, h[s], du * bl[s]);
            y = fmaf(h[s], cl[s], y);
        }
        y = fmaf(u, dval, y);
        float z = g_xz[(size_t)tok * 384 + DI + d];
        g_y[(size_t)tok * DI + d] = y * siluf(z);
    }
}

// ---------------------------------------------------------------------------
extern "C" void kernel_launch(void* const* d_in, const int* in_sizes, int n_in,
                              void* d_out, int out_size) {
    const float* x          = (const float*)d_in[0];
    const float* conv1234_w = (const float*)d_in[1];
    const float* conv1234_b = (const float*)d_in[2];
    const float* conv4321_w = (const float*)d_in[3];
    const float* conv4321_b = (const float*)d_in[4];
    const float* ln_g       = (const float*)d_in[5];
    const float* ln_b       = (const float*)d_in[6];
    const float* in_proj_w  = (const float*)d_in[7];
    const float* conv1d_w   = (const float*)d_in[8];
    const float* conv1d_b   = (const float*)d_in[9];
    const float* x_proj_w   = (const float*)d_in[10];
    const float* dt_proj_w  = (const float*)d_in[11];
    const float* dt_proj_b  = (const float*)d_in[12];
    const float* A_log      = (const float*)d_in[13];
    const float* Dp         = (const float*)d_in[14];
    const float* out_proj_w = (const float*)d_in[15];
    const float* fc1_w      = (const float*)d_in[16];
    const float* fc1_b      = (const float*)d_in[17];
    const float* fc2_w      = (const float*)d_in[18];
    const float* fc2_b      = (const float*)d_in[19];
    float* out = (float*)d_out;

    float *tcat, *xz, *xc, *xdbl, *y, *mo, *outssm, *lnbuf, *mid;
    cudaGetSymbolAddress((void**)&tcat,   g_tcat);
    cudaGetSymbolAddress((void**)&xz,     g_xz);
    cudaGetSymbolAddress((void**)&xc,     g_xc);
    cudaGetSymbolAddress((void**)&xdbl,   g_xdbl);
    cudaGetSymbolAddress((void**)&y,      g_y);
    cudaGetSymbolAddress((void**)&mo,     g_mo);
    cudaGetSymbolAddress((void**)&outssm, g_outssm);
    cudaGetSymbolAddress((void**)&lnbuf,  g_lnbuf);
    cudaGetSymbolAddress((void**)&mid,    g_mid);

    // 1+2) conv 1x3 (both dirs) fused with LN -> g_tcat directly
    const int CONV_SMEM = 128 * 98 * 4;   // 50176 B (> As+Ws3 = 28672 B)
    cudaFuncSetAttribute(conv13_ln_kernel,
                         cudaFuncAttributeMaxDynamicSharedMemorySize, CONV_SMEM);
    conv13_ln_kernel<<<512, 256, CONV_SMEM>>>(x, conv1234_w, conv1234_b,
                                              conv4321_w, conv4321_b, ln_g, ln_b);

    // 3) in_proj: [65536,96] @ [384,96]^T -> g_xz
    {
        dim3 grid(TTOK/256, 4);
        gemm_tf32_kernel<96,0,false,false><<<grid, 256>>>(tcat, in_proj_w, nullptr, nullptr, xz, TTOK, 384, CCH);
    }

    // 4) depthwise conv1d + silu -> g_xc
    conv1d_kernel<<<(TTOK/4*48)/256, 256>>>(xz, conv1d_w, conv1d_b);

    // 5) x_proj: [65536,192] @ [38,192]^T -> g_xdbl  (BN=48 tile)
    {
        dim3 grid(TTOK/256, 1);
        gemm_tf32_kernel<48,0,false,false><<<grid, 256>>>(xc, x_proj_w, nullptr, nullptr, xdbl, TTOK, NXD, DI);
    }

    // 6) dt projection + softplus -> g_dt
    dt_kernel<<<(TTOK*48)/256, 256>>>(dt_proj_w, dt_proj_b);

    // 7-9) chunked selective scan
    scan1_kernel<<<NSEQ*NCH, 192>>>(A_log);
    scan2_kernel<<<(NSEQ*DI*DS)/256, 256>>>();
    scan3_kernel<<<NSEQ*NCH, 192>>>(A_log, Dp);

    // 10) out_proj: [65536,192] @ [96,192]^T -> g_mo
    {
        dim3 grid(TTOK/256, 1);
        gemm_tf32_kernel<96,0,false,false><<<grid, 256>>>(y, out_proj_w, nullptr, nullptr, mo, TTOK, CCH, DI);
    }

    // 11+12) fused combine + LN -> g_outssm, g_lnbuf
    combine_ln_kernel<<<TOK2/8, 256>>>(ln_g, ln_b);

    // 13) fc1 + gelu -> g_mid
    {
        dim3 grid(TOK2/256, 1);
        gemm_tf32_kernel<96,1,true,false><<<grid, 256>>>(lnbuf, fc1_w, fc1_b, nullptr, mid, TOK2, CCH, CCH);
    }

    // 14) fc2 + bias + residual(out_ssm) -> d_out
    {
        dim3 grid(TOK2/256, 1);
        gemm_tf32_kernel<96,0,true,true><<<grid, 256>>>(mid, fc2_w, fc2_b, outssm, out, TOK2, CCH, CCH);
    }
}